// round 7
// baseline (speedup 1.0000x reference)
#include <cuda_runtime.h>
#include <cstdint>
#include <cstddef>

// Shapes (fixed)
#define NB 16
#define NM 128
#define NH 256
#define NE 128
#define NC 384
#define NROWS 2048
#define EDGE_GRID 148

// Scratch: msg_e only (2048 x 128)
__device__ float g_msgE[NROWS * NE];

// ---------------------------------------------------------------------------
// helpers
// ---------------------------------------------------------------------------
__device__ __forceinline__ uint32_t f2tf(float x) {
    uint32_t r;
    asm("cvt.rna.tf32.f32 %0, %1;" : "=r"(r) : "f"(x));
    return r;
}
__device__ __forceinline__ uint4 cvt4(float4 v) {
    return make_uint4(f2tf(v.x), f2tf(v.y), f2tf(v.z), f2tf(v.w));
}
__device__ __forceinline__ void mma8(float* d, const uint32_t* a, const uint32_t* b) {
    asm volatile(
        "mma.sync.aligned.m16n8k8.row.col.f32.tf32.tf32.f32 "
        "{%0,%1,%2,%3}, {%4,%5,%6,%7}, {%8,%9}, {%0,%1,%2,%3};"
        : "+f"(d[0]), "+f"(d[1]), "+f"(d[2]), "+f"(d[3])
        : "r"(a[0]), "r"(a[1]), "r"(a[2]), "r"(a[3]),
          "r"(b[0]), "r"(b[1]));
}

// ---------------------------------------------------------------------------
// Edge kernel SMEM layout (floats)
// ---------------------------------------------------------------------------
#define ES_PITCH 132
#define WS_PITCH 136
#define SM_ES 0
#define SM_WS (128 * ES_PITCH)               // 16896
#define SM_AW (SM_WS + 128 * WS_PITCH)       // 34304
#define SM_RED (SM_AW + 256)                 // 34560
#define SM_FLOATS (SM_RED + 384)             // 34944
#define SM_BYTES (SM_FLOATS * 4)             // 139776

// compute one k-quarter (32 e = 4 ksteps) for a warp's 32x32 block
__device__ __forceinline__ void compute_quarter(const float* __restrict__ ap,
                                                const float* __restrict__ bp,
                                                float acc[2][4][4])
{
    #pragma unroll
    for (int ss = 0; ss < 4; ++ss) {
        uint32_t a[2][4];
        #pragma unroll
        for (int m = 0; m < 2; ++m) {
            const float* p = ap + m * (16 * ES_PITCH) + ss * 8;
            a[m][0] = __float_as_uint(p[0]);
            a[m][1] = __float_as_uint(p[8 * ES_PITCH]);
            a[m][2] = __float_as_uint(p[4]);
            a[m][3] = __float_as_uint(p[8 * ES_PITCH + 4]);
        }
        uint32_t bq[4][2];
        #pragma unroll
        for (int n = 0; n < 4; ++n) {
            const float* p = bp + ss * (8 * WS_PITCH) + n * 8;
            bq[n][0] = __float_as_uint(p[0]);
            bq[n][1] = __float_as_uint(p[4 * WS_PITCH]);
        }
        #pragma unroll
        for (int m = 0; m < 2; ++m)
            #pragma unroll
            for (int n = 0; n < 4; ++n)
                mma8(acc[m][n], a[m], bq[n]);
    }
}

// ---------------------------------------------------------------------------
// Edge kernel: persistent, tf32 mma, 512 threads = 16 warps (4 rg x 4 cg).
// Per tile t=(b,j): D[i,f] = sum_e E[b,i,j,e]*We[e,f];
//                   msg_e[f] = sum_i A[b,i,j]*relu(D[i,f]+be[f])
// ---------------------------------------------------------------------------
__global__ __launch_bounds__(512, 1)
void edge_msg_mma(const float* __restrict__ E,
                  const float* __restrict__ A,
                  const float* __restrict__ We,
                  const float* __restrict__ be,
                  float* __restrict__ msgE)
{
    extern __shared__ float sm[];
    float* Es  = sm + SM_ES;
    float* Ws  = sm + SM_WS;
    float* awb = sm + SM_AW;
    float* red = sm + SM_RED;

    const int tid  = threadIdx.x;
    const int lane = tid & 31;
    const int wid  = tid >> 5;
    const int rg   = wid >> 2;          // 0..3: rows rg*32..+31
    const int cg   = wid & 3;           // 0..3: cols cg*32..+31
    const int row0 = rg * 32;
    const int col0 = cg * 32;

    float be0[4], be1[4];
    #pragma unroll
    for (int n = 0; n < 4; ++n) {
        be0[n] = be[col0 + 8 * n + 2 * (lane & 3)];
        be1[n] = be[col0 + 8 * n + 2 * (lane & 3) + 1];
    }

    // We -> SMEM (tf32). 512 threads: f-chunk (tid&31)*4, rows (tid>>5)+16q
    {
        const float* wsrc = We + (size_t)(tid >> 5) * 128 + (tid & 31) * 4;
        float* wdst = Ws + (tid >> 5) * WS_PITCH + (tid & 31) * 4;
        #pragma unroll
        for (int q = 0; q < 8; ++q)
            *(uint4*)(wdst + q * (16 * WS_PITCH)) = cvt4(*(const float4*)(wsrc + q * 2048));
    }

    const int t0  = blockIdx.x;
    const int ntl = (NROWS - t0 + EDGE_GRID - 1) / EDGE_GRID;

    // E quarter loader: 128 i x 32 e. thread: e-chunk (tid&7)*4, rows (tid>>3)+64r
    const int ech = (tid & 7) * 4;
    const int ir0 = tid >> 3;           // 0..63
    auto ldq = [&](float4* r, int t, int q) {
        const float* src = E + (size_t)(t >> 7) * 2097152
                             + (size_t)ir0 * 16384
                             + (size_t)(t & 127) * 128 + q * 32 + ech;
        r[0] = *(const float4*)(src);
        r[1] = *(const float4*)(src + (size_t)64 * 16384);
    };
    float* qdst0 = Es + ir0 * ES_PITCH + ech;

    float4 pre[2];
    ldq(pre, t0, 0);
    float awreg = (tid < 128)
        ? A[(size_t)(t0 >> 7) * 16384 + (size_t)tid * 128 + (t0 & 127)] : 0.f;

    float acc[2][4][4];
    #pragma unroll
    for (int m = 0; m < 2; ++m)
        #pragma unroll
        for (int n = 0; n < 4; ++n)
            #pragma unroll
            for (int q = 0; q < 4; ++q) acc[m][n][q] = 0.f;

    const float* aptr = Es + (row0 + (lane >> 2)) * ES_PITCH + (lane & 3);
    const float* bptr = Ws + (lane & 3) * WS_PITCH + col0 + (lane >> 2);

    for (int k = 0; k < ntl; ++k) {
        const int t = t0 + k * EDGE_GRID;
        const bool hn = (k + 1 < ntl);

        #pragma unroll
        for (int q = 0; q < 4; ++q) {
            float* qd = qdst0 + q * 32;
            *(uint4*)(qd)                       = cvt4(pre[0]);
            *(uint4*)(qd + 64 * ES_PITCH)       = cvt4(pre[1]);

            if (q == 0 && tid < 128) {
                awb[(k & 1) * 128 + tid] = awreg;
                if (hn) {
                    const int tn = t + EDGE_GRID;
                    awreg = A[(size_t)(tn >> 7) * 16384 + (size_t)tid * 128 + (tn & 127)];
                }
            }
            if (q < 3)       ldq(pre, t, q + 1);
            else if (hn)     ldq(pre, t + EDGE_GRID, 0);

            __syncthreads();
            compute_quarter(aptr + q * 32, bptr + q * (32 * WS_PITCH), acc);
        }

        // ---- epilogue: bias+relu, weight by A, reduce over i ----
        {
            const float* aw = awb + (k & 1) * 128;
            float p0[4], p1[4];
            #pragma unroll
            for (int n = 0; n < 4; ++n) { p0[n] = 0.f; p1[n] = 0.f; }
            #pragma unroll
            for (int m = 0; m < 2; ++m) {
                float w0 = aw[row0 + 16 * m + (lane >> 2)];
                float w1 = aw[row0 + 16 * m + (lane >> 2) + 8];
                #pragma unroll
                for (int n = 0; n < 4; ++n) {
                    p0[n] += w0 * fmaxf(acc[m][n][0] + be0[n], 0.f)
                           + w1 * fmaxf(acc[m][n][2] + be0[n], 0.f);
                    p1[n] += w0 * fmaxf(acc[m][n][1] + be1[n], 0.f)
                           + w1 * fmaxf(acc[m][n][3] + be1[n], 0.f);
                    acc[m][n][0] = 0.f; acc[m][n][1] = 0.f;
                    acc[m][n][2] = 0.f; acc[m][n][3] = 0.f;
                }
            }
            #pragma unroll
            for (int off = 4; off < 32; off <<= 1) {
                #pragma unroll
                for (int n = 0; n < 4; ++n) {
                    p0[n] += __shfl_xor_sync(0xffffffffu, p0[n], off);
                    p1[n] += __shfl_xor_sync(0xffffffffu, p1[n], off);
                }
            }
            if (rg > 0 && lane < 4) {
                #pragma unroll
                for (int n = 0; n < 4; ++n) {
                    int f = col0 + 8 * n + 2 * lane;
                    red[(rg - 1) * 128 + f]     = p0[n];
                    red[(rg - 1) * 128 + f + 1] = p1[n];
                }
            }
            __syncthreads();
            if (rg == 0 && lane < 4) {
                #pragma unroll
                for (int n = 0; n < 4; ++n) {
                    int f = col0 + 8 * n + 2 * lane;
                    msgE[(size_t)t * NE + f] =
                        p0[n] + red[f] + red[128 + f] + red[256 + f];
                    msgE[(size_t)t * NE + f + 1] =
                        p1[n] + red[f + 1] + red[128 + f + 1] + red[256 + f + 1];
                }
            }
        }
    }
}

// ---------------------------------------------------------------------------
// Fused MLP + msg_x: one CTA owns 16 rows (one batch b, j0..j0+15).
//   msg_x = A_b^T X_b (scalar, in-SMEM) ; Am = [msg_x | msg_e] (tf32)
//   t = (1+eps)*X + relu(Am@Wr + br); u = relu(t@W0+b0); out = relu(u@W1+b1)
// 256 threads = 8 warps, warp tile 16x32. grid 128.
// ---------------------------------------------------------------------------
#define FA_PITCH 388
#define FT_PITCH 260
#define FB_PITCH 264
#define XC_PITCH 260
#define OF_TS (16 * FA_PITCH)            // 6208
#define OF_US (OF_TS + 16 * FT_PITCH)    // 10368
#define OF_BS (OF_US + 16 * FT_PITCH)    // 14528
#define FSM_FLOATS (OF_BS + 2 * 32 * FB_PITCH)   // 31424
#define FSM_BYTES (FSM_FLOATS * 4)               // 125696

__device__ __forceinline__ void fgemm(const float* __restrict__ Asm, int PA,
                                      const float* __restrict__ W,
                                      float* __restrict__ bs0,
                                      float* __restrict__ bs1,
                                      int nch, int tid, int lane, int wcol0,
                                      float acc[4][4])
{
    const int bk  = tid >> 3;
    const int bc0 = (tid & 7) * 4;
    const float* wsrc = W + (size_t)bk * 256 + bc0;

    float4 pw[8];
    #pragma unroll
    for (int q = 0; q < 8; ++q) pw[q] = *(const float4*)(wsrc + 32 * q);

    for (int kc = 0; kc < nch; ++kc) {
        float* bd = ((kc & 1) ? bs1 : bs0) + bk * FB_PITCH + bc0;
        #pragma unroll
        for (int q = 0; q < 8; ++q) *(uint4*)(bd + 32 * q) = cvt4(pw[q]);
        if (kc + 1 < nch) {
            const float* ws = wsrc + (size_t)(kc + 1) * 32 * 256;
            #pragma unroll
            for (int q = 0; q < 8; ++q) pw[q] = *(const float4*)(ws + 32 * q);
        }
        __syncthreads();

        const float* ap = Asm + (lane >> 2) * PA + (lane & 3) + kc * 32;
        const float* bp = ((kc & 1) ? bs1 : bs0) + (lane & 3) * FB_PITCH
                        + wcol0 + (lane >> 2);
        #pragma unroll
        for (int ss = 0; ss < 4; ++ss) {
            uint32_t a[4];
            const float* p = ap + ss * 8;
            a[0] = __float_as_uint(p[0]);
            a[1] = __float_as_uint(p[8 * PA]);
            a[2] = __float_as_uint(p[4]);
            a[3] = __float_as_uint(p[8 * PA + 4]);
            uint32_t bq[4][2];
            #pragma unroll
            for (int n = 0; n < 4; ++n) {
                const float* p2 = bp + ss * (8 * FB_PITCH) + n * 8;
                bq[n][0] = __float_as_uint(p2[0]);
                bq[n][1] = __float_as_uint(p2[4 * FB_PITCH]);
            }
            #pragma unroll
            for (int n = 0; n < 4; ++n) mma8(acc[n], a, bq[n]);
        }
        __syncthreads();
    }
}

__global__ __launch_bounds__(256)
void mlp_fused(const float* __restrict__ msgE,
               const float* __restrict__ X,
               const float* __restrict__ A,
               const float* __restrict__ epsp,
               const float* __restrict__ Wr, const float* __restrict__ br,
               const float* __restrict__ W0, const float* __restrict__ b0,
               const float* __restrict__ W1, const float* __restrict__ b1,
               float* __restrict__ Out)
{
    extern __shared__ float fsm[];
    float* Am  = fsm;
    float* Ts  = fsm + OF_TS;
    float* Us  = fsm + OF_US;
    float* bs0 = fsm + OF_BS;
    float* bs1 = fsm + OF_BS + 32 * FB_PITCH;
    // prologue scratch aliases the W buffers
    float* As2 = fsm + OF_BS;            // 128 x 16
    float* Xc  = fsm + OF_BS + 2048;     // 16 x XC_PITCH

    const int r0   = blockIdx.x * 16;
    const int b    = r0 >> 7;
    const int j0   = r0 & 127;
    const int tid  = threadIdx.x;
    const int lane = tid & 31;
    const int wid  = tid >> 5;
    const int wcol0 = wid * 32;

    // stage A block A[b, i, j0+jj]  (i=0..127, jj=0..15)
    for (int idx = tid; idx < 2048; idx += 256) {
        int i = idx >> 4, jj = idx & 15;
        As2[i * 16 + jj] = A[(size_t)b * 16384 + (size_t)i * 128 + j0 + jj];
    }
    // stage msg_e into Am cols 256..383 (tf32)
    {
        const int row = tid >> 4;
        const int c   = (tid & 15) * 8;
        const float* src = msgE + (size_t)(r0 + row) * NE + c;
        float* dst = Am + row * FA_PITCH + 256 + c;
        *(uint4*)(dst)     = cvt4(*(const float4*)(src));
        *(uint4*)(dst + 4) = cvt4(*(const float4*)(src + 4));
    }
    __syncthreads();

    // msg_x = A_b^T X_b for 16 j rows: thread = (j = tid>>4, h segs (tid&15)*4 + 64q)
    {
        const int j  = tid >> 4;
        const int h0 = (tid & 15) * 4;
        float macc[16];
        #pragma unroll
        for (int q = 0; q < 16; ++q) macc[q] = 0.f;

        for (int ch = 0; ch < 8; ++ch) {
            // stage X chunk: rows ii = tid>>4, cols (tid&15)*16
            {
                const int ii = tid >> 4;
                const int c  = (tid & 15) * 16;
                const float* src = X + (size_t)b * 32768
                                 + (size_t)(ch * 16 + ii) * 256 + c;
                float* dst = Xc + ii * XC_PITCH + c;
                #pragma unroll
                for (int q = 0; q < 4; ++q)
                    *(float4*)(dst + 4 * q) = *(const float4*)(src + 4 * q);
            }
            __syncthreads();
            #pragma unroll
            for (int ii = 0; ii < 16; ++ii) {
                float a = As2[(ch * 16 + ii) * 16 + j];
                #pragma unroll
                for (int q = 0; q < 4; ++q) {
                    float4 xv = *(const float4*)(Xc + ii * XC_PITCH + h0 + 64 * q);
                    macc[q * 4 + 0] += a * xv.x;
                    macc[q * 4 + 1] += a * xv.y;
                    macc[q * 4 + 2] += a * xv.z;
                    macc[q * 4 + 3] += a * xv.w;
                }
            }
            __syncthreads();
        }
        // write msg_x (tf32) into Am cols 0..255
        #pragma unroll
        for (int q = 0; q < 4; ++q) {
            float4 v = make_float4(macc[q * 4], macc[q * 4 + 1],
                                   macc[q * 4 + 2], macc[q * 4 + 3]);
            *(uint4*)(Am + j * FA_PITCH + h0 + 64 * q) = cvt4(v);
        }
    }
    __syncthreads();

    float acc[4][4];
    #pragma unroll
    for (int n = 0; n < 4; ++n)
        #pragma unroll
        for (int q = 0; q < 4; ++q) acc[n][q] = 0.f;

    // ---- layer 1: t = (1+eps)*X + relu(Am@Wr + br) ----
    fgemm(Am, FA_PITCH, Wr, bs0, bs1, 12, tid, lane, wcol0, acc);
    {
        const float epsv = 1.f + *epsp;
        #pragma unroll
        for (int n = 0; n < 4; ++n)
            #pragma unroll
            for (int q = 0; q < 4; ++q) {
                int row = (lane >> 2) + ((q & 2) ? 8 : 0);
                int col = wcol0 + 8 * n + 2 * (lane & 3) + (q & 1);
                float v = fmaxf(acc[n][q] + br[col], 0.f)
                        + epsv * X[(size_t)(r0 + row) * 256 + col];
                Ts[row * FT_PITCH + col] = __uint_as_float(f2tf(v));
                acc[n][q] = 0.f;
            }
    }
    __syncthreads();

    // ---- layer 2: u = relu(t@W0 + b0) ----
    fgemm(Ts, FT_PITCH, W0, bs0, bs1, 8, tid, lane, wcol0, acc);
    {
        #pragma unroll
        for (int n = 0; n < 4; ++n)
            #pragma unroll
            for (int q = 0; q < 4; ++q) {
                int row = (lane >> 2) + ((q & 2) ? 8 : 0);
                int col = wcol0 + 8 * n + 2 * (lane & 3) + (q & 1);
                float v = fmaxf(acc[n][q] + b0[col], 0.f);
                Us[row * FT_PITCH + col] = __uint_as_float(f2tf(v));
                acc[n][q] = 0.f;
            }
    }
    __syncthreads();

    // ---- layer 3: out = relu(u@W1 + b1) ----
    fgemm(Us, FT_PITCH, W1, bs0, bs1, 8, tid, lane, wcol0, acc);
    {
        #pragma unroll
        for (int n = 0; n < 4; ++n)
            #pragma unroll
            for (int q = 0; q < 4; ++q) {
                int row = (lane >> 2) + ((q & 2) ? 8 : 0);
                int col = wcol0 + 8 * n + 2 * (lane & 3) + (q & 1);
                Out[(size_t)(r0 + row) * 256 + col] = fmaxf(acc[n][q] + b1[col], 0.f);
            }
    }
}

// ---------------------------------------------------------------------------
extern "C" void kernel_launch(void* const* d_in, const int* in_sizes, int n_in,
                              void* d_out, int out_size)
{
    const float* X   = (const float*)d_in[0];
    const float* E   = (const float*)d_in[1];
    const float* A   = (const float*)d_in[2];
    const float* eps = (const float*)d_in[3];
    const float* We  = (const float*)d_in[4];
    const float* be  = (const float*)d_in[5];
    const float* Wr  = (const float*)d_in[6];
    const float* br  = (const float*)d_in[7];
    const float* W0  = (const float*)d_in[8];
    const float* b0  = (const float*)d_in[9];
    const float* W1  = (const float*)d_in[10];
    const float* b1  = (const float*)d_in[11];
    float* out = (float*)d_out;

    void* pmsg;
    cudaGetSymbolAddress(&pmsg, g_msgE);
    float* msgE = (float*)pmsg;

    cudaFuncSetAttribute(edge_msg_mma,
                         cudaFuncAttributeMaxDynamicSharedMemorySize, SM_BYTES);
    cudaFuncSetAttribute(mlp_fused,
                         cudaFuncAttributeMaxDynamicSharedMemorySize, FSM_BYTES);

    edge_msg_mma<<<EDGE_GRID, 512, SM_BYTES>>>(E, A, We, be, msgE);
    mlp_fused<<<128, 256, FSM_BYTES>>>(msgE, X, A, eps, Wr, br, W0, b0, W1, b1, out);
}

// round 8
// speedup vs baseline: 1.2595x; 1.2595x over previous
#include <cuda_runtime.h>
#include <cuda_fp16.h>
#include <cstdint>
#include <cstddef>

// Shapes (fixed)
#define NB 16
#define NM 128
#define NH 256
#define NE 128
#define NC 384
#define NROWS 2048
#define EDGE_GRID 148

// Scratch: msg_e only (2048 x 128)
__device__ float g_msgE[NROWS * NE];

// ---------------------------------------------------------------------------
// helpers
// ---------------------------------------------------------------------------
__device__ __forceinline__ uint32_t f2tf(float x) {
    uint32_t r;
    asm("cvt.rna.tf32.f32 %0, %1;" : "=r"(r) : "f"(x));
    return r;
}
__device__ __forceinline__ uint4 cvt4(float4 v) {
    return make_uint4(f2tf(v.x), f2tf(v.y), f2tf(v.z), f2tf(v.w));
}
// tf32 m16n8k8
__device__ __forceinline__ void mma8(float* d, const uint32_t* a, const uint32_t* b) {
    asm volatile(
        "mma.sync.aligned.m16n8k8.row.col.f32.tf32.tf32.f32 "
        "{%0,%1,%2,%3}, {%4,%5,%6,%7}, {%8,%9}, {%0,%1,%2,%3};"
        : "+f"(d[0]), "+f"(d[1]), "+f"(d[2]), "+f"(d[3])
        : "r"(a[0]), "r"(a[1]), "r"(a[2]), "r"(a[3]),
          "r"(b[0]), "r"(b[1]));
}
// fp16 m16n8k16 (same 10-bit mantissa as tf32, 2x K per instruction)
__device__ __forceinline__ void mma16h(float* d, const uint32_t* a, const uint32_t* b) {
    asm volatile(
        "mma.sync.aligned.m16n8k16.row.col.f32.f16.f16.f32 "
        "{%0,%1,%2,%3}, {%4,%5,%6,%7}, {%8,%9}, {%0,%1,%2,%3};"
        : "+f"(d[0]), "+f"(d[1]), "+f"(d[2]), "+f"(d[3])
        : "r"(a[0]), "r"(a[1]), "r"(a[2]), "r"(a[3]),
          "r"(b[0]), "r"(b[1]));
}
__device__ __forceinline__ uint32_t h2u(half2 h) {
    return *reinterpret_cast<uint32_t*>(&h);
}

// ---------------------------------------------------------------------------
// Edge kernel: fp16 m16n8k16, 512 threads = 16 warps (4 rg x 4 cg), persistent.
// Per tile t=(b,j): D[i,f] = sum_e E[b,i,j,e]*We[e,f];
//                   msg_e[f] = sum_i A[b,i,j]*relu(D[i,f]+be[f])
// SMEM (bytes): Es 128x136 halfs | Ws(=We^T [f][e]) 128x136 halfs | aw | red
// ---------------------------------------------------------------------------
#define EH_PITCH 136   // halfs; /2 = 68 banks == 4 mod 32 -> conflict-free frags
#define ES_OFF   0
#define WS_OFF   34816
#define AW_OFF   69632
#define RED_OFF  70656
#define SM_BYTES 72192

// one k-quarter (32 e = 2 ksteps of 16) for a warp's 32x32 block
__device__ __forceinline__ void compute_quarter_h(const half* __restrict__ ap,
                                                  const half* __restrict__ bp,
                                                  float acc[2][4][4])
{
    #pragma unroll
    for (int ss = 0; ss < 2; ++ss) {
        const int kb = ss * 16;
        uint32_t a[2][4];
        #pragma unroll
        for (int m = 0; m < 2; ++m) {
            const half* p = ap + m * (16 * EH_PITCH) + kb;
            a[m][0] = *(const uint32_t*)(p);
            a[m][1] = *(const uint32_t*)(p + 8 * EH_PITCH);
            a[m][2] = *(const uint32_t*)(p + 8);
            a[m][3] = *(const uint32_t*)(p + 8 * EH_PITCH + 8);
        }
        uint32_t bq[4][2];
        #pragma unroll
        for (int n = 0; n < 4; ++n) {
            const half* p = bp + n * (8 * EH_PITCH) + kb;
            bq[n][0] = *(const uint32_t*)(p);
            bq[n][1] = *(const uint32_t*)(p + 8);
        }
        #pragma unroll
        for (int m = 0; m < 2; ++m)
            #pragma unroll
            for (int n = 0; n < 4; ++n)
                mma16h(acc[m][n], a[m], bq[n]);
    }
}

__global__ __launch_bounds__(512, 1)
void edge_msg_mma(const float* __restrict__ E,
                  const float* __restrict__ A,
                  const float* __restrict__ We,
                  const float* __restrict__ be,
                  float* __restrict__ msgE)
{
    extern __shared__ char smc[];
    half*  Es  = (half*)(smc + ES_OFF);
    half*  Ws  = (half*)(smc + WS_OFF);
    float* awb = (float*)(smc + AW_OFF);
    float* red = (float*)(smc + RED_OFF);

    const int tid  = threadIdx.x;
    const int lane = tid & 31;
    const int wid  = tid >> 5;
    const int rg   = wid >> 2;
    const int cg   = wid & 3;
    const int row0 = rg * 32;
    const int col0 = cg * 32;

    float be0[4], be1[4];
    #pragma unroll
    for (int n = 0; n < 4; ++n) {
        be0[n] = be[col0 + 8 * n + 2 * (lane & 3)];
        be1[n] = be[col0 + 8 * n + 2 * (lane & 3) + 1];
    }

    // We^T -> Ws[f][e] as half2 pairs (once). idx: f = idx&127, e-pair = idx>>7
    for (int idx = tid; idx < 8192; idx += 512) {
        int f = idx & 127;
        int e = (idx >> 7) * 2;
        float v0 = We[(size_t)e * 128 + f];
        float v1 = We[(size_t)(e + 1) * 128 + f];
        *(half2*)(Ws + f * EH_PITCH + e) = __floats2half2_rn(v0, v1);
    }

    const int t0  = blockIdx.x;
    const int ntl = (NROWS - t0 + EDGE_GRID - 1) / EDGE_GRID;

    // E quarter loader: thread e-chunk (tid&7)*4, rows (tid>>3) + {0,64}
    const int ech = (tid & 7) * 4;
    const int ir0 = tid >> 3;           // 0..63
    auto ldq = [&](float4* r, int t, int q) {
        const float* src = E + (size_t)(t >> 7) * 2097152
                             + (size_t)ir0 * 16384
                             + (size_t)(t & 127) * 128 + q * 32 + ech;
        r[0] = *(const float4*)(src);
        r[1] = *(const float4*)(src + (size_t)64 * 16384);
    };
    half* qdst0 = Es + ir0 * EH_PITCH + ech;

    float4 pre[2];
    ldq(pre, t0, 0);
    float awreg = (tid < 128)
        ? A[(size_t)(t0 >> 7) * 16384 + (size_t)tid * 128 + (t0 & 127)] : 0.f;

    float acc[2][4][4];
    #pragma unroll
    for (int m = 0; m < 2; ++m)
        #pragma unroll
        for (int n = 0; n < 4; ++n)
            #pragma unroll
            for (int q = 0; q < 4; ++q) acc[m][n][q] = 0.f;

    const half* aptr = Es + (row0 + (lane >> 2)) * EH_PITCH + (lane & 3) * 2;
    const half* bptr = Ws + (col0 + (lane >> 2)) * EH_PITCH + (lane & 3) * 2;

    for (int k = 0; k < ntl; ++k) {
        const int t = t0 + k * EDGE_GRID;
        const bool hn = (k + 1 < ntl);

        #pragma unroll
        for (int q = 0; q < 4; ++q) {
            half* qd = qdst0 + q * 32;
            {
                half2 h0 = __floats2half2_rn(pre[0].x, pre[0].y);
                half2 h1 = __floats2half2_rn(pre[0].z, pre[0].w);
                *(uint2*)(qd) = make_uint2(h2u(h0), h2u(h1));
                half2 h2 = __floats2half2_rn(pre[1].x, pre[1].y);
                half2 h3 = __floats2half2_rn(pre[1].z, pre[1].w);
                *(uint2*)(qd + 64 * EH_PITCH) = make_uint2(h2u(h2), h2u(h3));
            }
            if (q == 0 && tid < 128) {
                awb[(k & 1) * 128 + tid] = awreg;
                if (hn) {
                    const int tn = t + EDGE_GRID;
                    awreg = A[(size_t)(tn >> 7) * 16384 + (size_t)tid * 128 + (tn & 127)];
                }
            }
            if (q < 3)       ldq(pre, t, q + 1);
            else if (hn)     ldq(pre, t + EDGE_GRID, 0);

            __syncthreads();
            compute_quarter_h(aptr + q * 32, bptr + q * 32, acc);
        }

        // ---- epilogue: bias+relu, weight by A, reduce over i ----
        {
            const float* aw = awb + (k & 1) * 128;
            float p0[4], p1[4];
            #pragma unroll
            for (int n = 0; n < 4; ++n) { p0[n] = 0.f; p1[n] = 0.f; }
            #pragma unroll
            for (int m = 0; m < 2; ++m) {
                float w0 = aw[row0 + 16 * m + (lane >> 2)];
                float w1 = aw[row0 + 16 * m + (lane >> 2) + 8];
                #pragma unroll
                for (int n = 0; n < 4; ++n) {
                    p0[n] += w0 * fmaxf(acc[m][n][0] + be0[n], 0.f)
                           + w1 * fmaxf(acc[m][n][2] + be0[n], 0.f);
                    p1[n] += w0 * fmaxf(acc[m][n][1] + be1[n], 0.f)
                           + w1 * fmaxf(acc[m][n][3] + be1[n], 0.f);
                    acc[m][n][0] = 0.f; acc[m][n][1] = 0.f;
                    acc[m][n][2] = 0.f; acc[m][n][3] = 0.f;
                }
            }
            #pragma unroll
            for (int off = 4; off < 32; off <<= 1) {
                #pragma unroll
                for (int n = 0; n < 4; ++n) {
                    p0[n] += __shfl_xor_sync(0xffffffffu, p0[n], off);
                    p1[n] += __shfl_xor_sync(0xffffffffu, p1[n], off);
                }
            }
            if (rg > 0 && lane < 4) {
                #pragma unroll
                for (int n = 0; n < 4; ++n) {
                    int f = col0 + 8 * n + 2 * lane;
                    red[(rg - 1) * 128 + f]     = p0[n];
                    red[(rg - 1) * 128 + f + 1] = p1[n];
                }
            }
            __syncthreads();
            if (rg == 0 && lane < 4) {
                #pragma unroll
                for (int n = 0; n < 4; ++n) {
                    int f = col0 + 8 * n + 2 * lane;
                    msgE[(size_t)t * NE + f] =
                        p0[n] + red[f] + red[128 + f] + red[256 + f];
                    msgE[(size_t)t * NE + f + 1] =
                        p1[n] + red[f + 1] + red[128 + f + 1] + red[256 + f + 1];
                }
            }
        }
    }
}

// ---------------------------------------------------------------------------
// Fused MLP + msg_x (all tf32 mma): one CTA = 16 rows (one b, j0..j0+15).
// 256 threads = 8 warps, warp tile 16x32. grid 128.
// ---------------------------------------------------------------------------
#define FA_PITCH 388
#define FT_PITCH 260
#define FB_PITCH 264
#define OF_TS (16 * FA_PITCH)            // 6208
#define OF_US (OF_TS + 16 * FT_PITCH)    // 10368
#define OF_BS (OF_US + 16 * FT_PITCH)    // 14528
#define FSM_FLOATS (OF_BS + 2 * 32 * FB_PITCH)   // 31424
#define FSM_BYTES (FSM_FLOATS * 4)               // 125696

// single-sync-per-chunk GEMM phase
__device__ __forceinline__ void fgemm(const float* __restrict__ Asm, int PA,
                                      const float* __restrict__ W,
                                      float* __restrict__ bs0,
                                      float* __restrict__ bs1,
                                      int nch, int tid, int lane, int wcol0,
                                      float acc[4][4])
{
    const int bk  = tid >> 3;
    const int bc0 = (tid & 7) * 4;
    const float* wsrc = W + (size_t)bk * 256 + bc0;

    float4 pw[8];
    #pragma unroll
    for (int q = 0; q < 8; ++q) pw[q] = *(const float4*)(wsrc + 32 * q);

    for (int kc = 0; kc < nch; ++kc) {
        float* bd = ((kc & 1) ? bs1 : bs0) + bk * FB_PITCH + bc0;
        #pragma unroll
        for (int q = 0; q < 8; ++q) *(uint4*)(bd + 32 * q) = cvt4(pw[q]);
        if (kc + 1 < nch) {
            const float* ws = wsrc + (size_t)(kc + 1) * 32 * 256;
            #pragma unroll
            for (int q = 0; q < 8; ++q) pw[q] = *(const float4*)(ws + 32 * q);
        }
        __syncthreads();   // STS(kc) visible; also fences buffer reuse (see proof)

        const float* ap = Asm + (lane >> 2) * PA + (lane & 3) + kc * 32;
        const float* bp = ((kc & 1) ? bs1 : bs0) + (lane & 3) * FB_PITCH
                        + wcol0 + (lane >> 2);
        #pragma unroll
        for (int ss = 0; ss < 4; ++ss) {
            uint32_t a[4];
            const float* p = ap + ss * 8;
            a[0] = __float_as_uint(p[0]);
            a[1] = __float_as_uint(p[8 * PA]);
            a[2] = __float_as_uint(p[4]);
            a[3] = __float_as_uint(p[8 * PA + 4]);
            uint32_t bq[4][2];
            #pragma unroll
            for (int n = 0; n < 4; ++n) {
                const float* p2 = bp + ss * (8 * FB_PITCH) + n * 8;
                bq[n][0] = __float_as_uint(p2[0]);
                bq[n][1] = __float_as_uint(p2[4 * FB_PITCH]);
            }
            #pragma unroll
            for (int n = 0; n < 4; ++n) mma8(acc[n], a, bq[n]);
        }
    }
}

__global__ __launch_bounds__(256)
void mlp_fused(const float* __restrict__ msgE,
               const float* __restrict__ X,
               const float* __restrict__ A,
               const float* __restrict__ epsp,
               const float* __restrict__ Wr, const float* __restrict__ br,
               const float* __restrict__ W0, const float* __restrict__ b0,
               const float* __restrict__ W1, const float* __restrict__ b1,
               float* __restrict__ Out)
{
    extern __shared__ float fsm[];
    float* Am  = fsm;
    float* Ts  = fsm + OF_TS;      // doubles as AsT (A-block^T) in the prologue
    float* Us  = fsm + OF_US;
    float* bs0 = fsm + OF_BS;
    float* bs1 = fsm + OF_BS + 32 * FB_PITCH;

    const int r0   = blockIdx.x * 16;
    const int b    = r0 >> 7;
    const int j0   = r0 & 127;
    const int tid  = threadIdx.x;
    const int lane = tid & 31;
    const int wid  = tid >> 5;
    const int wcol0 = wid * 32;

    // stage AsT[jj][i] = tf32(A[b, i, j0+jj])  (16 x 128, pitch 132, in Ts)
    for (int idx = tid; idx < 2048; idx += 256) {
        int i = idx >> 4, jj = idx & 15;
        float v = A[(size_t)b * 16384 + (size_t)i * 128 + j0 + jj];
        Ts[jj * 132 + i] = __uint_as_float(f2tf(v));
    }
    // stage msg_e into Am cols 256..383 (tf32)
    {
        const int row = tid >> 4;
        const int c   = (tid & 15) * 8;
        const float* src = msgE + (size_t)(r0 + row) * NE + c;
        float* dst = Am + row * FA_PITCH + 256 + c;
        *(uint4*)(dst)     = cvt4(*(const float4*)(src));
        *(uint4*)(dst + 4) = cvt4(*(const float4*)(src + 4));
    }
    __syncthreads();

    float acc[4][4];
    #pragma unroll
    for (int n = 0; n < 4; ++n)
        #pragma unroll
        for (int q = 0; q < 4; ++q) acc[n][q] = 0.f;

    // ---- msg_x = AsT @ X_b  (16 x 128) @ (128 x 256), tf32 mma ----
    fgemm(Ts, 132, X + (size_t)b * 32768, bs0, bs1, 4, tid, lane, wcol0, acc);
    {
        #pragma unroll
        for (int n = 0; n < 4; ++n)
            #pragma unroll
            for (int q = 0; q < 4; ++q) {
                int row = (lane >> 2) + ((q & 2) ? 8 : 0);
                int col = wcol0 + 8 * n + 2 * (lane & 3) + (q & 1);
                Am[row * FA_PITCH + col] = __uint_as_float(f2tf(acc[n][q]));
                acc[n][q] = 0.f;
            }
    }
    __syncthreads();

    // ---- layer 1: t = (1+eps)*X + relu(Am@Wr + br) ----
    fgemm(Am, FA_PITCH, Wr, bs0, bs1, 12, tid, lane, wcol0, acc);
    {
        const float epsv = 1.f + *epsp;
        #pragma unroll
        for (int n = 0; n < 4; ++n)
            #pragma unroll
            for (int q = 0; q < 4; ++q) {
                int row = (lane >> 2) + ((q & 2) ? 8 : 0);
                int col = wcol0 + 8 * n + 2 * (lane & 3) + (q & 1);
                float v = fmaxf(acc[n][q] + br[col], 0.f)
                        + epsv * X[(size_t)(r0 + row) * 256 + col];
                Ts[row * FT_PITCH + col] = __uint_as_float(f2tf(v));
                acc[n][q] = 0.f;
            }
    }
    __syncthreads();

    // ---- layer 2: u = relu(t@W0 + b0) ----
    fgemm(Ts, FT_PITCH, W0, bs0, bs1, 8, tid, lane, wcol0, acc);
    {
        #pragma unroll
        for (int n = 0; n < 4; ++n)
            #pragma unroll
            for (int q = 0; q < 4; ++q) {
                int row = (lane >> 2) + ((q & 2) ? 8 : 0);
                int col = wcol0 + 8 * n + 2 * (lane & 3) + (q & 1);
                float v = fmaxf(acc[n][q] + b0[col], 0.f);
                Us[row * FT_PITCH + col] = __uint_as_float(f2tf(v));
                acc[n][q] = 0.f;
            }
    }
    __syncthreads();

    // ---- layer 3: out = relu(u@W1 + b1) ----
    fgemm(Us, FT_PITCH, W1, bs0, bs1, 8, tid, lane, wcol0, acc);
    {
        #pragma unroll
        for (int n = 0; n < 4; ++n)
            #pragma unroll
            for (int q = 0; q < 4; ++q) {
                int row = (lane >> 2) + ((q & 2) ? 8 : 0);
                int col = wcol0 + 8 * n + 2 * (lane & 3) + (q & 1);
                Out[(size_t)(r0 + row) * 256 + col] = fmaxf(acc[n][q] + b1[col], 0.f);
            }
    }
}

// ---------------------------------------------------------------------------
extern "C" void kernel_launch(void* const* d_in, const int* in_sizes, int n_in,
                              void* d_out, int out_size)
{
    const float* X   = (const float*)d_in[0];
    const float* E   = (const float*)d_in[1];
    const float* A   = (const float*)d_in[2];
    const float* eps = (const float*)d_in[3];
    const float* We  = (const float*)d_in[4];
    const float* be  = (const float*)d_in[5];
    const float* Wr  = (const float*)d_in[6];
    const float* br  = (const float*)d_in[7];
    const float* W0  = (const float*)d_in[8];
    const float* b0  = (const float*)d_in[9];
    const float* W1  = (const float*)d_in[10];
    const float* b1  = (const float*)d_in[11];
    float* out = (float*)d_out;

    void* pmsg;
    cudaGetSymbolAddress(&pmsg, g_msgE);
    float* msgE = (float*)pmsg;

    cudaFuncSetAttribute(edge_msg_mma,
                         cudaFuncAttributeMaxDynamicSharedMemorySize, SM_BYTES);
    cudaFuncSetAttribute(mlp_fused,
                         cudaFuncAttributeMaxDynamicSharedMemorySize, FSM_BYTES);

    edge_msg_mma<<<EDGE_GRID, 512, SM_BYTES>>>(E, A, We, be, msgE);
    mlp_fused<<<128, 256, FSM_BYTES>>>(msgE, X, A, eps, Wr, br, W0, b0, W1, b1, out);
}